// round 3
// baseline (speedup 1.0000x reference)
#include <cuda_runtime.h>
#include <math.h>

#define NB 16
#define CDIM 256
#define TDIM 1024
#define CTXL 48
#define TGTR 1072      // CTXL + TDIM
#define FFD 1024
#define NLAYER 4
#define NHEAD 8
#define DHEAD 32
#define NWIN 64
#define WLEN 64

// scratch (static device globals — no allocation)
__device__ float g_tgt[NB * TGTR * CDIM];
__device__ float g_qkv[NB * TGTR * 3 * CDIM];
__device__ float g_att[NB * TDIM * CDIM];
__device__ float g_x1 [NB * TDIM * CDIM];
__device__ float g_ff [NB * TDIM * FFD];

// ---------------- depthwise causal conv (Le=32) ----------------
// out[b,t,c] = sum_l x[b,c,t-31+l] * filt[b,c,l], filt = mean over emb axis 1
__global__ void conv_kernel(const float* __restrict__ x, const float* __restrict__ emb) {
    int b = blockIdx.y;
    int t0 = blockIdx.x * 16;
    int c = threadIdx.x;
    float f[32];
#pragma unroll
    for (int l = 0; l < 32; l++)
        f[l] = 0.5f * (emb[((b * 2 + 0) * CDIM + c) * 32 + l] +
                       emb[((b * 2 + 1) * CDIM + c) * 32 + l]);
    float xv[47];
    const float* xr = x + ((long)(b * CDIM + c)) * TDIM;
#pragma unroll
    for (int l = 0; l < 47; l++) {
        int t = t0 - 31 + l;
        xv[l] = (t >= 0) ? xr[t] : 0.0f;
    }
#pragma unroll
    for (int tt = 0; tt < 16; tt++) {
        float s = 0.0f;
#pragma unroll
        for (int l = 0; l < 32; l++) s += xv[tt + l] * f[l];
        g_tgt[((long)(b * TGTR + CTXL + t0 + tt)) * CDIM + c] = s;
    }
}

// ---------------- per-layer prep: ctx snapshot + ctx load ----------------
__global__ void prep_kernel(const float* __restrict__ ctx_in, float* __restrict__ ctx_out,
                            int layer, int write_ctx) {
    int b = blockIdx.x;
    long snap_base = ((long)(b * TGTR + TDIM)) * CDIM;        // rows 1024..1071 (current output tail)
    long tgt_base  = ((long)(b * TGTR)) * CDIM;               // rows 0..47
    long io_base   = ((long)((b * NLAYER + layer) * CTXL)) * CDIM;
    for (int i = threadIdx.x; i < CTXL * CDIM; i += blockDim.x) {
        if (write_ctx) ctx_out[io_base + i] = g_tgt[snap_base + i];
        g_tgt[tgt_base + i] = ctx_in[io_base + i];
    }
}

// ---------------- SGEMM: out[M,N] = A[M,K] @ W[N,K]^T + bias, epilogues ----------------
// EPI: 0 = +bias, 1 = +bias + res (res ld = CDIM), 2 = +bias then relu
// 128x128 tile, 16-wide k-step, double-buffered smem with register prefetch.
template<int EPI>
__global__ void __launch_bounds__(256) gemm_kernel(
    const float* __restrict__ A, const float* __restrict__ W,
    const float* __restrict__ bias, const float* __restrict__ res,
    float* __restrict__ out, int K, int N, int res_remap, int out_remap)
{
    __shared__ float As[2][16][132];
    __shared__ float Ws[2][16][132];
    int tid = threadIdx.x;
    int tx = tid & 15, ty = tid >> 4;
    int m0 = blockIdx.y * 128, n0 = blockIdx.x * 128;

    float acc[8][8];
#pragma unroll
    for (int i = 0; i < 8; i++)
#pragma unroll
        for (int j = 0; j < 8; j++) acc[i][j] = 0.0f;

    int lr = tid >> 2;          // 0..63
    int lc = (tid & 3) * 4;     // 0,4,8,12

    const float* Ap0 = &A[((long)(m0 + lr))      * K + lc];
    const float* Ap1 = &A[((long)(m0 + lr + 64)) * K + lc];
    const float* Wp0 = &W[((long)(n0 + lr))      * K + lc];
    const float* Wp1 = &W[((long)(n0 + lr + 64)) * K + lc];

    // prologue: tile 0 -> buf 0
    {
        float4 a0 = *(const float4*)Ap0;
        float4 a1 = *(const float4*)Ap1;
        float4 w0 = *(const float4*)Wp0;
        float4 w1 = *(const float4*)Wp1;
        As[0][lc + 0][lr] = a0.x; As[0][lc + 1][lr] = a0.y; As[0][lc + 2][lr] = a0.z; As[0][lc + 3][lr] = a0.w;
        As[0][lc + 0][lr + 64] = a1.x; As[0][lc + 1][lr + 64] = a1.y; As[0][lc + 2][lr + 64] = a1.z; As[0][lc + 3][lr + 64] = a1.w;
        Ws[0][lc + 0][lr] = w0.x; Ws[0][lc + 1][lr] = w0.y; Ws[0][lc + 2][lr] = w0.z; Ws[0][lc + 3][lr] = w0.w;
        Ws[0][lc + 0][lr + 64] = w1.x; Ws[0][lc + 1][lr + 64] = w1.y; Ws[0][lc + 2][lr + 64] = w1.z; Ws[0][lc + 3][lr + 64] = w1.w;
    }
    __syncthreads();

    int KT = K >> 4;
    int cur = 0;
    for (int kt = 0; kt < KT; kt++) {
        float4 na0, na1, nw0, nw1;
        bool more = (kt + 1 < KT);
        if (more) {
            int off = (kt + 1) << 4;
            na0 = *(const float4*)(Ap0 + off);
            na1 = *(const float4*)(Ap1 + off);
            nw0 = *(const float4*)(Wp0 + off);
            nw1 = *(const float4*)(Wp1 + off);
        }
#pragma unroll
        for (int kk = 0; kk < 16; kk++) {
            float a[8], bb[8];
#pragma unroll
            for (int i = 0; i < 4; i++) { a[i] = As[cur][kk][ty * 4 + i]; a[4 + i] = As[cur][kk][64 + ty * 4 + i]; }
#pragma unroll
            for (int j = 0; j < 4; j++) { bb[j] = Ws[cur][kk][tx * 4 + j]; bb[4 + j] = Ws[cur][kk][64 + tx * 4 + j]; }
#pragma unroll
            for (int i = 0; i < 8; i++)
#pragma unroll
                for (int j = 0; j < 8; j++) acc[i][j] += a[i] * bb[j];
        }
        if (more) {
            int nxt = cur ^ 1;
            As[nxt][lc + 0][lr] = na0.x; As[nxt][lc + 1][lr] = na0.y; As[nxt][lc + 2][lr] = na0.z; As[nxt][lc + 3][lr] = na0.w;
            As[nxt][lc + 0][lr + 64] = na1.x; As[nxt][lc + 1][lr + 64] = na1.y; As[nxt][lc + 2][lr + 64] = na1.z; As[nxt][lc + 3][lr + 64] = na1.w;
            Ws[nxt][lc + 0][lr] = nw0.x; Ws[nxt][lc + 1][lr] = nw0.y; Ws[nxt][lc + 2][lr] = nw0.z; Ws[nxt][lc + 3][lr] = nw0.w;
            Ws[nxt][lc + 0][lr + 64] = nw1.x; Ws[nxt][lc + 1][lr + 64] = nw1.y; Ws[nxt][lc + 2][lr + 64] = nw1.z; Ws[nxt][lc + 3][lr + 64] = nw1.w;
            __syncthreads();
            cur = nxt;
        }
    }

#pragma unroll
    for (int i = 0; i < 8; i++) {
        int row = m0 + ((i < 4) ? (ty * 4 + i) : (64 + ty * 4 + i - 4));
        int rrow = res_remap ? (row + 48 * (row >> 10) + 48) : row;
        int orow = out_remap ? (row + 48 * (row >> 10) + 48) : row;
#pragma unroll
        for (int j = 0; j < 8; j++) {
            int col = n0 + ((j < 4) ? (tx * 4 + j) : (64 + tx * 4 + j - 4));
            float v = acc[i][j] + bias[col];
            if (EPI == 1) v += res[((long)rrow) * CDIM + col];
            if (EPI == 2) v = fmaxf(v, 0.0f);
            out[((long)orow) * N + col] = v;
        }
    }
}

// ---------------- LayerNorm (in place), warp per row of 256 ----------------
__global__ void ln_kernel(float* __restrict__ buf, const float* __restrict__ g,
                          const float* __restrict__ bt, int remap) {
    int row = blockIdx.x * 8 + (threadIdx.x >> 5);
    int lane = threadIdx.x & 31;
    int br = remap ? (row + 48 * (row >> 10) + 48) : row;
    float* p = buf + ((long)br) * CDIM + lane * 8;
    float4 v0 = *(float4*)p;
    float4 v1 = *(float4*)(p + 4);
    float v[8] = {v0.x, v0.y, v0.z, v0.w, v1.x, v1.y, v1.z, v1.w};
    float s = 0.0f;
#pragma unroll
    for (int i = 0; i < 8; i++) s += v[i];
#pragma unroll
    for (int o = 16; o > 0; o >>= 1) s += __shfl_xor_sync(0xffffffffu, s, o);
    float mu = s * (1.0f / 256.0f);
    float sq = 0.0f;
#pragma unroll
    for (int i = 0; i < 8; i++) { float d = v[i] - mu; sq += d * d; }
#pragma unroll
    for (int o = 16; o > 0; o >>= 1) sq += __shfl_xor_sync(0xffffffffu, sq, o);
    float rstd = rsqrtf(sq * (1.0f / 256.0f) + 1e-5f);
#pragma unroll
    for (int i = 0; i < 8; i++) {
        int c = lane * 8 + i;
        v[i] = (v[i] - mu) * rstd * g[c] + bt[c];
    }
    *(float4*)p       = make_float4(v[0], v[1], v[2], v[3]);
    *(float4*)(p + 4) = make_float4(v[4], v[5], v[6], v[7]);
}

// ---------------- windowed attention, online softmax, 16-token slabs ----------------
// block = (b, w), 128 threads = (head, qi). K+V staged 16 tokens at a time (32KB static smem).
__global__ void __launch_bounds__(128) attn_kernel() {
    __shared__ float sK[16 * 256];    // 16 KB
    __shared__ float sV[16 * 256];    // 16 KB
    int b = blockIdx.x >> 6, w = blockIdx.x & 63;
    int tid = threadIdx.x;
    int h = tid >> 4, qi = tid & 15;
    long rbase = (long)b * TGTR + w * 16;      // token row of window start

    float q[32];
    const float* qp = g_qkv + (rbase + 48 + qi) * 768 + h * 32;
#pragma unroll
    for (int d = 0; d < 32; d++) q[d] = qp[d];

    float mx = -1e30f, sum = 0.0f;
    float o[32];
#pragma unroll
    for (int d = 0; d < 32; d++) o[d] = 0.0f;

    float4* sKf = (float4*)sK;
    float4* sVf = (float4*)sV;
    const float4* qkvf = (const float4*)g_qkv;

    for (int slab = 0; slab < 4; slab++) {
        __syncthreads();
        // load 16 tokens of K and V: 16*64 float4 each, 128 threads -> 8 each
#pragma unroll
        for (int i = tid; i < 1024; i += 128) {
            int jj = i >> 6, c4 = i & 63;
            long trow = rbase + slab * 16 + jj;
            sKf[i] = qkvf[trow * 192 + 64  + c4];
            sVf[i] = qkvf[trow * 192 + 128 + c4];
        }
        __syncthreads();
#pragma unroll
        for (int jj = 0; jj < 16; jj++) {
            const float* kp = sK + jj * 256 + h * 32;
            float s = 0.0f;
#pragma unroll
            for (int d = 0; d < 32; d++) s += q[d] * kp[d];
            s *= 0.17677669529663687f;         // 1/sqrt(32)
            float nm = fmaxf(mx, s);
            float corr = __expf(mx - nm);
            float p = __expf(s - nm);
            sum = sum * corr + p;
            const float* vp = sV + jj * 256 + h * 32;
#pragma unroll
            for (int d = 0; d < 32; d++) o[d] = o[d] * corr + p * vp[d];
            mx = nm;
        }
    }
    float inv = 1.0f / sum;
    float* op = g_att + ((long)(b * TDIM + w * 16 + qi)) * CDIM + h * 32;
#pragma unroll
    for (int d4 = 0; d4 < 8; d4++)
        ((float4*)op)[d4] = make_float4(o[d4 * 4] * inv, o[d4 * 4 + 1] * inv,
                                        o[d4 * 4 + 2] * inv, o[d4 * 4 + 3] * inv);
}

// ---------------- final transpose: g_tgt[b][48+t][c] -> out[b][c][t] ----------------
__global__ void out_transpose(float* __restrict__ outp) {
    __shared__ float tile[32][33];
    int b = blockIdx.z;
    int t0 = blockIdx.x * 32, c0 = blockIdx.y * 32;
    int tx = threadIdx.x, ty = threadIdx.y;
#pragma unroll
    for (int i = 0; i < 32; i += 8)
        tile[ty + i][tx] = g_tgt[((long)(b * TGTR + CTXL + t0 + ty + i)) * CDIM + c0 + tx];
    __syncthreads();
#pragma unroll
    for (int i = 0; i < 32; i += 8)
        outp[((long)(b * CDIM + c0 + ty + i)) * TDIM + t0 + tx] = tile[tx][ty + i];
}

extern "C" void kernel_launch(void* const* d_in, const int* in_sizes, int n_in,
                              void* d_out, int out_size) {
    const float* x      = (const float*)d_in[0];
    const float* emb    = (const float*)d_in[1];
    const float* ctx_in = (const float*)d_in[2];
    const float* Wqkv   = (const float*)d_in[3];
    const float* bqkv   = (const float*)d_in[4];
    const float* Wo     = (const float*)d_in[5];
    const float* bo     = (const float*)d_in[6];
    const float* W1     = (const float*)d_in[7];
    const float* b1     = (const float*)d_in[8];
    const float* W2     = (const float*)d_in[9];
    const float* b2     = (const float*)d_in[10];
    const float* ln1g   = (const float*)d_in[11];
    const float* ln1b   = (const float*)d_in[12];
    const float* ln3g   = (const float*)d_in[13];
    const float* ln3b   = (const float*)d_in[14];

    float* outp = (float*)d_out;
    float* ctx_out = outp + (long)NB * CDIM * TDIM;
    int write_ctx = (out_size >= NB * CDIM * TDIM + NB * NLAYER * CTXL * CDIM) ? 1 : 0;

    float *tgt, *qkv, *att, *x1, *ff;
    cudaGetSymbolAddress((void**)&tgt, g_tgt);
    cudaGetSymbolAddress((void**)&qkv, g_qkv);
    cudaGetSymbolAddress((void**)&att, g_att);
    cudaGetSymbolAddress((void**)&x1,  g_x1);
    cudaGetSymbolAddress((void**)&ff,  g_ff);

    conv_kernel<<<dim3(64, 16), 256>>>(x, emb);

    for (int l = 0; l < NLAYER; l++) {
        prep_kernel<<<NB, 256>>>(ctx_in, ctx_out, l, write_ctx);
        // QKV over all 1072 positions per batch: M=17152, N=768, K=256
        gemm_kernel<0><<<dim3(6, 134), 256>>>(tgt, Wqkv + (long)l * 768 * 256,
                                              bqkv + l * 768, nullptr, qkv, 256, 768, 0, 0);
        attn_kernel<<<NB * NWIN, 128>>>();
        // x1_pre = q_in + att @ Wo^T + bo : M=16384, N=256, K=256 (res = tgt rows remapped)
        gemm_kernel<1><<<dim3(2, 128), 256>>>(att, Wo + (long)l * 256 * 256,
                                              bo + l * 256, tgt, x1, 256, 256, 1, 0);
        ln_kernel<<<2048, 256>>>(x1, ln1g + l * 256, ln1b + l * 256, 0);
        // ff = relu(x1 @ W1^T + b1): M=16384, N=1024, K=256
        gemm_kernel<2><<<dim3(8, 128), 256>>>(x1, W1 + (long)l * 1024 * 256,
                                              b1 + l * 1024, nullptr, ff, 256, 1024, 0, 0);
        // tgt_new = x1 + ff @ W2^T + b2 : M=16384, N=256, K=1024, write into tgt (remapped rows)
        gemm_kernel<1><<<dim3(2, 128), 256>>>(ff, W2 + (long)l * 256 * 1024,
                                              b2 + l * 256, x1, tgt, 1024, 256, 0, 1);
        ln_kernel<<<2048, 256>>>(tgt, ln3g + l * 256, ln3b + l * 256, 1);
    }

    out_transpose<<<dim3(32, 8, 16), dim3(32, 8)>>>(outp);
}